// round 4
// baseline (speedup 1.0000x reference)
#include <cuda_runtime.h>

#define NB 32
#define NC 64
#define NS 64
#define NE 6   // distinct experts (PERM folds 8 gates onto 6)

// Scratch (device globals)
__device__ float g_c  [4 * 16 * 64 * 32];          // [band][xy][i(chan)][b]
__device__ float g_Wt2[4 * 16 * NE * 64 * 64];     // [band][xy][e][i][o]  (6.3MB)
__device__ float g_S  [4 * 32 * 16 * 64];          // [band][b][xy][o]  gate-combined - identity
__device__ float g_z  [NB * NC * 64];              // [b][chan][8*8] correction, pre-scaled 1/8
__device__ float g_Wsum[NB];

// ---------------------------------------------------------------------------
// kTA: fused weight transpose (blocks 0..383) + coefficient extraction
// (blocks 384..895, 4 (b,chan) pairs per block) + Wsum (block 0).
// ---------------------------------------------------------------------------
__global__ void kTA(const float* __restrict__ x,
                    const float* __restrict__ WL, const float* __restrict__ WH,
                    const float* __restrict__ lam) {
    int blk = blockIdx.x;
    int t = threadIdx.x;              // 0..255
    if (blk < 384) {
        // ---- transpose W into [band][xy][e][i][o] ----
        if (blk == 0 && t < 32) {
            const float* lp = lam + t * 8;
            g_Wsum[t] = lp[0]+lp[1]+lp[2]+lp[3]+lp[4]+lp[5]+lp[6]+lp[7];
        }
        int be = blk >> 4;            // band*6+e
        int rr = blk & 15;
        int band = be / NE, e = be % NE;
        const float* src;
        if (band == 0) src = WL + (size_t)e * 65536;
        else           src = WH + (size_t)(e * 3 + (band - 1)) * 65536;
        int io = t + 256 * rr;        // 0..4095
        const float* sp = src + (size_t)io * 16;
        float4 q0 = *(const float4*)(sp);
        float4 q1 = *(const float4*)(sp + 4);
        float4 q2 = *(const float4*)(sp + 8);
        float4 q3 = *(const float4*)(sp + 12);
        float v[16] = {q0.x,q0.y,q0.z,q0.w, q1.x,q1.y,q1.z,q1.w,
                       q2.x,q2.y,q2.z,q2.w, q3.x,q3.y,q3.z,q3.w};
        float* dbase = g_Wt2 + (size_t)band * 16 * 24576 + (size_t)e * 4096 + io;
#pragma unroll
        for (int xy = 0; xy < 16; xy++)
            dbase[(size_t)xy * 24576] = v[xy];
    } else {
        // ---- kA: 8x8 block sums -> ll3 -> level-4 bands ----
        __shared__ float ll3[4][64];
        int sub = t >> 6, tt = t & 63;
        int bc = ((blk - 384) << 2) + sub;     // 0..2047
        int i = tt >> 3, j = tt & 7;
        const float* xp = x + (size_t)bc * NS * NS + (size_t)i * 8 * NS + j * 8;
        float s = 0.f;
#pragma unroll
        for (int r = 0; r < 8; r++) {
            float4 a = *(const float4*)(xp + r * NS);
            float4 b = *(const float4*)(xp + r * NS + 4);
            s += a.x + a.y + a.z + a.w + b.x + b.y + b.z + b.w;
        }
        ll3[sub][tt] = s * 0.125f;
        __syncthreads();
        if (tt < 16) {
            int xy = tt;
            int xx = xy >> 2, yy = xy & 3;
            float a = ll3[sub][(2 * xx) * 8 + 2 * yy];
            float b = ll3[sub][(2 * xx) * 8 + 2 * yy + 1];
            float c = ll3[sub][(2 * xx + 1) * 8 + 2 * yy];
            float d = ll3[sub][(2 * xx + 1) * 8 + 2 * yy + 1];
            int bb = bc >> 6, ch = bc & 63;
            float v[4];
            v[0] = (a + b + c + d) * 0.5f;
            v[1] = (a + b - c - d) * 0.5f;
            v[2] = (a - b + c - d) * 0.5f;
            v[3] = (a - b - c + d) * 0.5f;
#pragma unroll
            for (int band = 0; band < 4; band++)
                g_c[((band * 16 + xy) * 64 + ch) * 32 + bb] = v[band];
        }
    }
}

// ---------------------------------------------------------------------------
// kB1: per (band,xy,o-half): S[b,o] = sum_{e,i} (w_e[b]*c[i,b]) * W_e[i,o]
//                                     - Wsum[b]*c[o,b]
// 128 blocks x 256 threads. 48KB smem holds gate-scaled LHS wc[e][i][b].
// Main loop: pure K=384 GEMM, thread tile 2b x 2o.
// ---------------------------------------------------------------------------
__global__ void kB1(const float* __restrict__ lam) {
    __shared__ float wcsh[NE * 64 * 32];          // 49152 B
    int blk = blockIdx.x;             // 0..127
    int band = blk >> 5;
    int xy = (blk >> 1) & 15;
    int oh = blk & 1;
    int t = threadIdx.x;

    // per-thread gate weights for b = t&31
    int bl = t & 31;
    const float* lp = lam + bl * 8;
    float wreg[6];
    wreg[0] = lp[0]; wreg[1] = lp[1]; wreg[2] = lp[2]; wreg[3] = lp[3];
    wreg[4] = lp[4] + lp[6]; wreg[5] = lp[5] + lp[7];

    const float* cbase = g_c + (size_t)(band * 16 + xy) * 2048;   // [i][b] flat
    // phase 1a: raw c into e0 region
#pragma unroll
    for (int r = 0; r < 8; r++) {
        int j = t + 256 * r;
        wcsh[j] = cbase[j];
    }
    __syncthreads();
    // phase 1b: e=1..5 scaled copies (reads e0 region = raw c)
#pragma unroll
    for (int r = 0; r < 40; r++) {
        int j = t + 256 * r;          // 0..10239
        int i = (j >> 5) & 63;
        int e = 1 + (j >> 11);
        wcsh[2048 + j] = wcsh[i * 32 + bl] * wreg[e];
    }
    __syncthreads();
    // phase 1c: scale e0 in place
#pragma unroll
    for (int r = 0; r < 8; r++) {
        int j = t + 256 * r;
        wcsh[j] *= wreg[0];
    }
    __syncthreads();

    // main GEMM: tile 2b x 2o
    int b0 = (t >> 4) * 2;
    int o0 = (t & 15) * 2 + oh * 32;
    const float* wbase = g_Wt2 + (size_t)(band * 16 + xy) * 24576 + o0;
    float a00 = 0.f, a01 = 0.f, a10 = 0.f, a11 = 0.f;
#pragma unroll 8
    for (int k = 0; k < 384; k++) {
        float2 wc2 = *(const float2*)(wcsh + k * 32 + b0);
        float2 wv2 = *(const float2*)(wbase + (size_t)k * 64);
        a00 += wc2.x * wv2.x; a01 += wc2.x * wv2.y;
        a10 += wc2.y * wv2.x; a11 += wc2.y * wv2.y;
    }

    // epilogue: subtract identity, write S[band][b][xy][o]
    float Wt0 = g_Wsum[b0], Wt1 = g_Wsum[b0 + 1];
    float o00 = cbase[(o0) * 32 + b0];
    float o01 = cbase[(o0 + 1) * 32 + b0];
    float o10 = cbase[(o0) * 32 + b0 + 1];
    float o11 = cbase[(o0 + 1) * 32 + b0 + 1];
    float* Sp0 = g_S + ((size_t)(band * 32 + b0) * 16 + xy) * 64 + o0;
    float* Sp1 = Sp0 + 16 * 64;
    *(float2*)Sp0 = make_float2(a00 - Wt0 * o00, a01 - Wt0 * o01);
    *(float2*)Sp1 = make_float2(a10 - Wt1 * o10, a11 - Wt1 * o11);
}

// ---------------------------------------------------------------------------
// kB2: pure 4x4->8x8 Haar IDWT of S, pre-scaled by 1/8. 32768 threads.
// ---------------------------------------------------------------------------
__global__ void kB2() {
    int g = blockIdx.x * blockDim.x + threadIdx.x;   // 0..32767
    int o = g & 63;
    int xy = (g >> 6) & 15;
    int b = g >> 10;
    float Sv[4];
#pragma unroll
    for (int band = 0; band < 4; band++)
        Sv[band] = g_S[(size_t)band * 32768 + ((size_t)b * 16 + xy) * 64 + o];
    float x00 = (Sv[0] + Sv[1] + Sv[2] + Sv[3]) * 0.0625f;
    float x01 = (Sv[0] + Sv[1] - Sv[2] - Sv[3]) * 0.0625f;
    float x10 = (Sv[0] - Sv[1] + Sv[2] - Sv[3]) * 0.0625f;
    float x11 = (Sv[0] - Sv[1] - Sv[2] + Sv[3]) * 0.0625f;
    int xx = xy >> 2, yy = xy & 3;
    float* zp = g_z + (size_t)(b * 64 + o) * 64;
    zp[(2 * xx) * 8 + 2 * yy]         = x00;
    zp[(2 * xx) * 8 + 2 * yy + 1]     = x01;
    zp[(2 * xx + 1) * 8 + 2 * yy]     = x10;
    zp[(2 * xx + 1) * 8 + 2 * yy + 1] = x11;
}

// ---------------------------------------------------------------------------
// kC: out = Wsum[b] * x + z[b,c,h/8,w/8].  16 consecutive floats per thread.
// ---------------------------------------------------------------------------
__global__ void kC(const float* __restrict__ x, float* __restrict__ out) {
    int tid = blockIdx.x * blockDim.x + threadIdx.x;  // 0..524287
    int e0 = tid << 4;
    int b = e0 >> 18;
    int c = (e0 >> 12) & 63;
    int h = (e0 >> 6) & 63;
    int w0 = e0 & 63;                 // 0,16,32,48
    float W = g_Wsum[b];
    const float* zq = g_z + (size_t)((b << 6) + c) * 64 + ((h >> 3) << 3);
    float zv0 = zq[(w0 >> 3)];
    float zv1 = zq[(w0 >> 3) + 1];
    float4 x0 = *(const float4*)(x + e0);
    float4 x1 = *(const float4*)(x + e0 + 4);
    float4 x2 = *(const float4*)(x + e0 + 8);
    float4 x3 = *(const float4*)(x + e0 + 12);
    float4 r0, r1, r2, r3;
    r0.x = fmaf(W, x0.x, zv0); r0.y = fmaf(W, x0.y, zv0);
    r0.z = fmaf(W, x0.z, zv0); r0.w = fmaf(W, x0.w, zv0);
    r1.x = fmaf(W, x1.x, zv0); r1.y = fmaf(W, x1.y, zv0);
    r1.z = fmaf(W, x1.z, zv0); r1.w = fmaf(W, x1.w, zv0);
    r2.x = fmaf(W, x2.x, zv1); r2.y = fmaf(W, x2.y, zv1);
    r2.z = fmaf(W, x2.z, zv1); r2.w = fmaf(W, x2.w, zv1);
    r3.x = fmaf(W, x3.x, zv1); r3.y = fmaf(W, x3.y, zv1);
    r3.z = fmaf(W, x3.z, zv1); r3.w = fmaf(W, x3.w, zv1);
    *(float4*)(out + e0)      = r0;
    *(float4*)(out + e0 + 4)  = r1;
    *(float4*)(out + e0 + 8)  = r2;
    *(float4*)(out + e0 + 12) = r3;
}

// ---------------------------------------------------------------------------
extern "C" void kernel_launch(void* const* d_in, const int* in_sizes, int n_in,
                              void* d_out, int out_size) {
    const float* x   = (const float*)d_in[0];  // [32,64,64,64]
    const float* lam = (const float*)d_in[1];  // [32,1,8,1]
    const float* WL  = (const float*)d_in[2];  // [8,64,64,4,4]
    const float* WH  = (const float*)d_in[3];  // [8,3,64,64,4,4]
    float* out = (float*)d_out;

    kTA<<<896, 256>>>(x, WL, WH, lam);
    kB1<<<128, 256>>>(lam);
    kB2<<<128, 256>>>();
    kC<<<2048, 256>>>(x, out);
    (void)in_sizes; (void)n_in; (void)out_size;
}

// round 5
// speedup vs baseline: 1.1370x; 1.1370x over previous
#include <cuda_runtime.h>

#define NB 32
#define NC 64
#define NS 64
#define NE 6   // distinct experts (PERM folds 8 gates onto 6)

// Scratch (device globals)
__device__ float g_c  [4 * 16 * 64 * 32];          // [band][xy][i(chan)][b]
__device__ float g_Wt2[4 * 16 * NE * 64 * 64];     // [band][xy][e][i][o]  (6.3MB)
__device__ float g_S  [4 * 32 * 16 * 64];          // [band][b][xy][o]
__device__ float g_Wsum[NB];

// ---------------------------------------------------------------------------
// kTA: fused weight transpose (blocks 0..383) + coefficient extraction
// (blocks 384..895) + Wsum (block 0).
// ---------------------------------------------------------------------------
__global__ void kTA(const float* __restrict__ x,
                    const float* __restrict__ WL, const float* __restrict__ WH,
                    const float* __restrict__ lam) {
    int blk = blockIdx.x;
    int t = threadIdx.x;              // 0..255
    if (blk < 384) {
        if (blk == 0 && t < 32) {
            const float* lp = lam + t * 8;
            g_Wsum[t] = lp[0]+lp[1]+lp[2]+lp[3]+lp[4]+lp[5]+lp[6]+lp[7];
        }
        int be = blk >> 4;            // band*6+e
        int rr = blk & 15;
        int band = be / NE, e = be % NE;
        const float* src;
        if (band == 0) src = WL + (size_t)e * 65536;
        else           src = WH + (size_t)(e * 3 + (band - 1)) * 65536;
        int io = t + 256 * rr;        // 0..4095
        const float* sp = src + (size_t)io * 16;
        float4 q0 = *(const float4*)(sp);
        float4 q1 = *(const float4*)(sp + 4);
        float4 q2 = *(const float4*)(sp + 8);
        float4 q3 = *(const float4*)(sp + 12);
        float v[16] = {q0.x,q0.y,q0.z,q0.w, q1.x,q1.y,q1.z,q1.w,
                       q2.x,q2.y,q2.z,q2.w, q3.x,q3.y,q3.z,q3.w};
        float* dbase = g_Wt2 + (size_t)band * 16 * 24576 + (size_t)e * 4096 + io;
#pragma unroll
        for (int xy = 0; xy < 16; xy++)
            dbase[(size_t)xy * 24576] = v[xy];
    } else {
        __shared__ float ll3[4][64];
        int sub = t >> 6, tt = t & 63;
        int bc = ((blk - 384) << 2) + sub;     // 0..2047
        int i = tt >> 3, j = tt & 7;
        const float* xp = x + (size_t)bc * NS * NS + (size_t)i * 8 * NS + j * 8;
        float s = 0.f;
#pragma unroll
        for (int r = 0; r < 8; r++) {
            float4 a = *(const float4*)(xp + r * NS);
            float4 b = *(const float4*)(xp + r * NS + 4);
            s += a.x + a.y + a.z + a.w + b.x + b.y + b.z + b.w;
        }
        ll3[sub][tt] = s * 0.125f;
        __syncthreads();
        if (tt < 16) {
            int xy = tt;
            int xx = xy >> 2, yy = xy & 3;
            float a = ll3[sub][(2 * xx) * 8 + 2 * yy];
            float b = ll3[sub][(2 * xx) * 8 + 2 * yy + 1];
            float c = ll3[sub][(2 * xx + 1) * 8 + 2 * yy];
            float d = ll3[sub][(2 * xx + 1) * 8 + 2 * yy + 1];
            int bb = bc >> 6, ch = bc & 63;
            float v[4];
            v[0] = (a + b + c + d) * 0.5f;
            v[1] = (a + b - c - d) * 0.5f;
            v[2] = (a - b + c - d) * 0.5f;
            v[3] = (a - b - c + d) * 0.5f;
#pragma unroll
            for (int band = 0; band < 4; band++)
                g_c[((band * 16 + xy) * 64 + ch) * 32 + bb] = v[band];
        }
    }
}

// ---------------------------------------------------------------------------
// kB1: per (band,xy,o-half): S[b,o] = sum_{e,i} (w_e[b]*c[i,b]) * W_e[i,o]
//                                     - Wsum[b]*c[o,b]
// 128 blocks x 256 threads, 48KB smem gate-scaled LHS, K=384 GEMM.
// ---------------------------------------------------------------------------
__global__ void kB1(const float* __restrict__ lam) {
    __shared__ float wcsh[NE * 64 * 32];          // 49152 B
    int blk = blockIdx.x;             // 0..127
    int band = blk >> 5;
    int xy = (blk >> 1) & 15;
    int oh = blk & 1;
    int t = threadIdx.x;

    int bl = t & 31;
    const float* lp = lam + bl * 8;
    float wreg[6];
    wreg[0] = lp[0]; wreg[1] = lp[1]; wreg[2] = lp[2]; wreg[3] = lp[3];
    wreg[4] = lp[4] + lp[6]; wreg[5] = lp[5] + lp[7];

    const float* cbase = g_c + (size_t)(band * 16 + xy) * 2048;   // [i][b]
#pragma unroll
    for (int r = 0; r < 8; r++) {
        int j = t + 256 * r;
        wcsh[j] = cbase[j];
    }
    __syncthreads();
#pragma unroll
    for (int r = 0; r < 40; r++) {
        int j = t + 256 * r;          // 0..10239
        int i = (j >> 5) & 63;
        int e = 1 + (j >> 11);
        wcsh[2048 + j] = wcsh[i * 32 + bl] * wreg[e];
    }
    __syncthreads();
#pragma unroll
    for (int r = 0; r < 8; r++) {
        int j = t + 256 * r;
        wcsh[j] *= wreg[0];
    }
    __syncthreads();

    int b0 = (t >> 4) * 2;
    int o0 = (t & 15) * 2 + oh * 32;
    const float* wbase = g_Wt2 + (size_t)(band * 16 + xy) * 24576 + o0;
    float a00 = 0.f, a01 = 0.f, a10 = 0.f, a11 = 0.f;
#pragma unroll 8
    for (int k = 0; k < 384; k++) {
        float2 wc2 = *(const float2*)(wcsh + k * 32 + b0);
        float2 wv2 = *(const float2*)(wbase + (size_t)k * 64);
        a00 += wc2.x * wv2.x; a01 += wc2.x * wv2.y;
        a10 += wc2.y * wv2.x; a11 += wc2.y * wv2.y;
    }

    float Wt0 = g_Wsum[b0], Wt1 = g_Wsum[b0 + 1];
    float o00 = cbase[(o0) * 32 + b0];
    float o01 = cbase[(o0 + 1) * 32 + b0];
    float o10 = cbase[(o0) * 32 + b0 + 1];
    float o11 = cbase[(o0 + 1) * 32 + b0 + 1];
    float* Sp0 = g_S + ((size_t)(band * 32 + b0) * 16 + xy) * 64 + o0;
    float* Sp1 = Sp0 + 16 * 64;
    *(float2*)Sp0 = make_float2(a00 - Wt0 * o00, a01 - Wt0 * o01);
    *(float2*)Sp1 = make_float2(a10 - Wt1 * o10, a11 - Wt1 * o11);
}

// ---------------------------------------------------------------------------
// kC: fused IDWT + AXPY.  One block per (b,c) image (2048 blocks, 256 thr).
// Threads 0..63 build the 8x8 z table in smem from g_S (IDWT, pre-scaled 1/8);
// then 4 warp-contiguous float4 slots per thread: out = Wsum*x + z.
// ---------------------------------------------------------------------------
__global__ void kC(const float* __restrict__ x, float* __restrict__ out) {
    __shared__ float zs[64];
    int bc = blockIdx.x;
    int t = threadIdx.x;
    int b = bc >> 6, c = bc & 63;

    if (t < 64) {
        int X = t >> 3, Y = t & 7;
        int xy = ((X >> 1) << 2) + (Y >> 1);
        float s1 = (X & 1) ? -1.f : 1.f;
        float s2 = (Y & 1) ? -1.f : 1.f;
        const float* Sp = g_S + ((size_t)b * 16 + xy) * 64 + c;
        float S0 = Sp[0];
        float S1 = Sp[32768];
        float S2 = Sp[65536];
        float S3 = Sp[98304];
        zs[t] = (S0 + s1 * S1 + s2 * S2 + (s1 * s2) * S3) * 0.0625f;
    }
    float W = g_Wsum[b];
    __syncthreads();

    const float* xp = x + (size_t)bc * 4096;
    float* op = out + (size_t)bc * 4096;
#pragma unroll
    for (int k = 0; k < 4; k++) {
        int idx = (t << 2) + (k << 10);          // warp-contiguous within slot
        float zv = zs[((idx >> 9) << 3) + ((idx & 63) >> 3)];  // (h>>3)*8 + (w>>3)
        float4 xv = *(const float4*)(xp + idx);
        float4 ov;
        ov.x = fmaf(W, xv.x, zv);
        ov.y = fmaf(W, xv.y, zv);
        ov.z = fmaf(W, xv.z, zv);
        ov.w = fmaf(W, xv.w, zv);
        *(float4*)(op + idx) = ov;
    }
}

// ---------------------------------------------------------------------------
extern "C" void kernel_launch(void* const* d_in, const int* in_sizes, int n_in,
                              void* d_out, int out_size) {
    const float* x   = (const float*)d_in[0];  // [32,64,64,64]
    const float* lam = (const float*)d_in[1];  // [32,1,8,1]
    const float* WL  = (const float*)d_in[2];  // [8,64,64,4,4]
    const float* WH  = (const float*)d_in[3];  // [8,3,64,64,4,4]
    float* out = (float*)d_out;

    kTA<<<896, 256>>>(x, WL, WH, lam);
    kB1<<<128, 256>>>(lam);
    kC<<<2048, 256>>>(x, out);
    (void)in_sizes; (void)n_in; (void)out_size;
}

// round 6
// speedup vs baseline: 1.5886x; 1.3971x over previous
#include <cuda_runtime.h>

#define NB 32
#define NC 64
#define NS 64
#define NE 6   // distinct experts (PERM folds 8 gates onto 6)

// Scratch (device globals)
__device__ float g_c  [4 * 16 * 64 * 32];          // [band][xy][i(chan)][b]
__device__ float g_Wt2[4 * 16 * NE * 64 * 64];     // [band][xy][e][i][o]  (6.3MB)
__device__ float g_S  [NE * 4 * 32 * 16 * 64];     // [e][band][b][xy][o]  (3MB)
__device__ float g_z  [NB * NC * 64];              // [b][c][XY]  z-table, pre-scaled 1/8
__device__ float g_Wsum[NB];

// ---------------------------------------------------------------------------
// kTA: fused weight transpose (blocks 0..383) + coefficient extraction
// (blocks 384..895) + Wsum (block 0).
// ---------------------------------------------------------------------------
__global__ void kTA(const float* __restrict__ x,
                    const float* __restrict__ WL, const float* __restrict__ WH,
                    const float* __restrict__ lam) {
    int blk = blockIdx.x;
    int t = threadIdx.x;              // 0..255
    if (blk < 384) {
        if (blk == 0 && t < 32) {
            const float* lp = lam + t * 8;
            g_Wsum[t] = lp[0]+lp[1]+lp[2]+lp[3]+lp[4]+lp[5]+lp[6]+lp[7];
        }
        int be = blk >> 4;            // band*6+e
        int rr = blk & 15;
        int band = be / NE, e = be % NE;
        const float* src;
        if (band == 0) src = WL + (size_t)e * 65536;
        else           src = WH + (size_t)(e * 3 + (band - 1)) * 65536;
        int io = t + 256 * rr;        // 0..4095
        const float* sp = src + (size_t)io * 16;
        float4 q0 = *(const float4*)(sp);
        float4 q1 = *(const float4*)(sp + 4);
        float4 q2 = *(const float4*)(sp + 8);
        float4 q3 = *(const float4*)(sp + 12);
        float v[16] = {q0.x,q0.y,q0.z,q0.w, q1.x,q1.y,q1.z,q1.w,
                       q2.x,q2.y,q2.z,q2.w, q3.x,q3.y,q3.z,q3.w};
        float* dbase = g_Wt2 + (size_t)band * 16 * 24576 + (size_t)e * 4096 + io;
#pragma unroll
        for (int xy = 0; xy < 16; xy++)
            dbase[(size_t)xy * 24576] = v[xy];
    } else {
        __shared__ float ll3[4][64];
        int sub = t >> 6, tt = t & 63;
        int bc = ((blk - 384) << 2) + sub;     // 0..2047
        int i = tt >> 3, j = tt & 7;
        const float* xp = x + (size_t)bc * NS * NS + (size_t)i * 8 * NS + j * 8;
        float s = 0.f;
#pragma unroll
        for (int r = 0; r < 8; r++) {
            float4 a = *(const float4*)(xp + r * NS);
            float4 b = *(const float4*)(xp + r * NS + 4);
            s += a.x + a.y + a.z + a.w + b.x + b.y + b.z + b.w;
        }
        ll3[sub][tt] = s * 0.125f;
        __syncthreads();
        if (tt < 16) {
            int xy = tt;
            int xx = xy >> 2, yy = xy & 3;
            float a = ll3[sub][(2 * xx) * 8 + 2 * yy];
            float b = ll3[sub][(2 * xx) * 8 + 2 * yy + 1];
            float c = ll3[sub][(2 * xx + 1) * 8 + 2 * yy];
            float d = ll3[sub][(2 * xx + 1) * 8 + 2 * yy + 1];
            int bb = bc >> 6, ch = bc & 63;
            float v[4];
            v[0] = (a + b + c + d) * 0.5f;
            v[1] = (a + b - c - d) * 0.5f;
            v[2] = (a - b + c - d) * 0.5f;
            v[3] = (a - b - c + d) * 0.5f;
#pragma unroll
            for (int band = 0; band < 4; band++)
                g_c[((band * 16 + xy) * 64 + ch) * 32 + bb] = v[band];
        }
    }
}

// ---------------------------------------------------------------------------
// kB1: one block per (band,xy,e): S_e[b,o] = sum_i (w_e[b]*c[i,b]) * W_e[i,o]
// (e==0 blocks also subtract Wt[b]*c[o,b]).  384 blocks x 256 threads,
// 8KB smem LHS, K=64, thread tile 2b x 4o.
// ---------------------------------------------------------------------------
__global__ void kB1(const float* __restrict__ lam) {
    __shared__ float wcsh[64 * 32];               // 8KB: [i][b] gate-scaled
    int blk = blockIdx.x;             // 0..383
    int e = blk % NE;
    int bx = blk / NE;
    int xy = bx & 15;
    int band = bx >> 4;
    int t = threadIdx.x;
    int bl = t & 31;

    const float* lp = lam + bl * 8;
    float we;
    if      (e == 0) we = lp[0];
    else if (e == 1) we = lp[1];
    else if (e == 2) we = lp[2];
    else if (e == 3) we = lp[3];
    else if (e == 4) we = lp[4] + lp[6];
    else             we = lp[5] + lp[7];

    const float* cbase = g_c + (size_t)(band * 16 + xy) * 2048;   // [i][b]
#pragma unroll
    for (int r = 0; r < 8; r++) {
        int j = t + 256 * r;
        wcsh[j] = cbase[j] * we;
    }
    __syncthreads();

    int b0 = (t >> 4) * 2;            // 0..30
    int o0 = (t & 15) * 4;            // 0..60
    const float* wbase = g_Wt2 + ((size_t)(band * 16 + xy) * NE + e) * 4096 + o0;
    float a0x = 0.f, a0y = 0.f, a0z = 0.f, a0w = 0.f;
    float a1x = 0.f, a1y = 0.f, a1z = 0.f, a1w = 0.f;
#pragma unroll 8
    for (int k = 0; k < 64; k++) {
        float2 c2 = *(const float2*)(wcsh + k * 32 + b0);
        float4 w4 = *(const float4*)(wbase + k * 64);
        a0x += c2.x * w4.x; a0y += c2.x * w4.y; a0z += c2.x * w4.z; a0w += c2.x * w4.w;
        a1x += c2.y * w4.x; a1y += c2.y * w4.y; a1z += c2.y * w4.z; a1w += c2.y * w4.w;
    }

    if (e == 0) {
        float Wt0 = g_Wsum[b0], Wt1 = g_Wsum[b0 + 1];
        a0x -= Wt0 * cbase[(o0    ) * 32 + b0];
        a0y -= Wt0 * cbase[(o0 + 1) * 32 + b0];
        a0z -= Wt0 * cbase[(o0 + 2) * 32 + b0];
        a0w -= Wt0 * cbase[(o0 + 3) * 32 + b0];
        a1x -= Wt1 * cbase[(o0    ) * 32 + b0 + 1];
        a1y -= Wt1 * cbase[(o0 + 1) * 32 + b0 + 1];
        a1z -= Wt1 * cbase[(o0 + 2) * 32 + b0 + 1];
        a1w -= Wt1 * cbase[(o0 + 3) * 32 + b0 + 1];
    }

    float* Sp = g_S + ((((size_t)e * 4 + band) * 32 + b0) * 16 + xy) * 64 + o0;
    *(float4*)Sp            = make_float4(a0x, a0y, a0z, a0w);
    *(float4*)(Sp + 16*64)  = make_float4(a1x, a1y, a1z, a1w);
}

// ---------------------------------------------------------------------------
// kR: sum S over 6 experts, apply per-band IDWT signs, write z-table
// g_z[b][c][XY] pre-scaled by 1/16 (IDWT 0.5 * three upsample levels 1/8).
// 512 blocks x 256 threads, tid -> (b, XY, c) c-fastest: coalesced loads.
// ---------------------------------------------------------------------------
__global__ void kR() {
    int tid = blockIdx.x * blockDim.x + threadIdx.x;  // 0..131071
    int c = tid & 63;
    int XY = (tid >> 6) & 63;
    int b = tid >> 12;
    int X = XY >> 3, Y = XY & 7;
    int xy = ((X >> 1) << 2) + (Y >> 1);
    float s1 = (X & 1) ? -1.f : 1.f;
    float s2 = (Y & 1) ? -1.f : 1.f;
    float s3 = s1 * s2;
    float z = 0.f;
#pragma unroll
    for (int e = 0; e < NE; e++) {
        const float* Sp = g_S + (((size_t)e * 4 * 32 + b) * 16 + xy) * 64 + c;
        z += Sp[0] + s1 * Sp[32768] + s2 * Sp[65536] + s3 * Sp[98304];
    }
    g_z[((size_t)b << 12) + (c << 6) + XY] = z * 0.0625f;
}

// ---------------------------------------------------------------------------
// kC: fused AXPY.  One block per (b,c) image (2048 blocks, 256 thr).
// Threads 0..63 load the contiguous 64-entry z table; then 4 warp-contiguous
// float4 slots per thread: out = Wsum*x + z.
// ---------------------------------------------------------------------------
__global__ void kC(const float* __restrict__ x, float* __restrict__ out) {
    __shared__ float zs[64];
    int bc = blockIdx.x;
    int t = threadIdx.x;
    int b = bc >> 6;

    if (t < 64) zs[t] = g_z[((size_t)bc << 6) + t];
    float W = g_Wsum[b];
    __syncthreads();

    const float* xp = x + (size_t)bc * 4096;
    float* op = out + (size_t)bc * 4096;
#pragma unroll
    for (int k = 0; k < 4; k++) {
        int idx = (t << 2) + (k << 10);          // warp-contiguous within slot
        float zv = zs[((idx >> 9) << 3) + ((idx & 63) >> 3)];  // X*8 + Y
        float4 xv = *(const float4*)(xp + idx);
        float4 ov;
        ov.x = fmaf(W, xv.x, zv);
        ov.y = fmaf(W, xv.y, zv);
        ov.z = fmaf(W, xv.z, zv);
        ov.w = fmaf(W, xv.w, zv);
        *(float4*)(op + idx) = ov;
    }
}

// ---------------------------------------------------------------------------
extern "C" void kernel_launch(void* const* d_in, const int* in_sizes, int n_in,
                              void* d_out, int out_size) {
    const float* x   = (const float*)d_in[0];  // [32,64,64,64]
    const float* lam = (const float*)d_in[1];  // [32,1,8,1]
    const float* WL  = (const float*)d_in[2];  // [8,64,64,4,4]
    const float* WH  = (const float*)d_in[3];  // [8,3,64,64,4,4]
    float* out = (float*)d_out;

    kTA<<<896, 256>>>(x, WL, WH, lam);
    kB1<<<384, 256>>>(lam);
    kR<<<512, 256>>>();
    kC<<<2048, 256>>>(x, out);
    (void)in_sizes; (void)n_in; (void)out_size;
}

// round 7
// speedup vs baseline: 1.5984x; 1.0061x over previous
#include <cuda_runtime.h>

#define NB 32
#define NC 64
#define NS 64
#define NE 6   // distinct experts (PERM folds 8 gates onto 6)

// Scratch (device globals)
__device__ float g_c  [4 * 16 * 64 * 32];          // [band][xy][i(chan)][b]
__device__ float g_Wt2[4 * 16 * NE * 64 * 64];     // [band][xy][e][i][o]  (6.3MB)
__device__ float g_S  [32 * 16 * 24 * 64];         // [b][xy][e*4+band][o]  (3MB)
__device__ float g_Wsum[NB];

// ---------------------------------------------------------------------------
// kTA: fused weight transpose (blocks 0..383) + coefficient extraction
// (blocks 384..895) + Wsum (block 0).
// ---------------------------------------------------------------------------
__global__ void kTA(const float* __restrict__ x,
                    const float* __restrict__ WL, const float* __restrict__ WH,
                    const float* __restrict__ lam) {
    int blk = blockIdx.x;
    int t = threadIdx.x;              // 0..255
    if (blk < 384) {
        if (blk == 0 && t < 32) {
            const float* lp = lam + t * 8;
            g_Wsum[t] = lp[0]+lp[1]+lp[2]+lp[3]+lp[4]+lp[5]+lp[6]+lp[7];
        }
        int be = blk >> 4;            // band*6+e
        int rr = blk & 15;
        int band = be / NE, e = be % NE;
        const float* src;
        if (band == 0) src = WL + (size_t)e * 65536;
        else           src = WH + (size_t)(e * 3 + (band - 1)) * 65536;
        int io = t + 256 * rr;        // 0..4095
        const float* sp = src + (size_t)io * 16;
        float4 q0 = *(const float4*)(sp);
        float4 q1 = *(const float4*)(sp + 4);
        float4 q2 = *(const float4*)(sp + 8);
        float4 q3 = *(const float4*)(sp + 12);
        float v[16] = {q0.x,q0.y,q0.z,q0.w, q1.x,q1.y,q1.z,q1.w,
                       q2.x,q2.y,q2.z,q2.w, q3.x,q3.y,q3.z,q3.w};
        float* dbase = g_Wt2 + (size_t)band * 16 * 24576 + (size_t)e * 4096 + io;
#pragma unroll
        for (int xy = 0; xy < 16; xy++)
            dbase[(size_t)xy * 24576] = v[xy];
    } else {
        __shared__ float ll3[4][64];
        int sub = t >> 6, tt = t & 63;
        int bc = ((blk - 384) << 2) + sub;     // 0..2047
        int i = tt >> 3, j = tt & 7;
        const float* xp = x + (size_t)bc * NS * NS + (size_t)i * 8 * NS + j * 8;
        float s = 0.f;
#pragma unroll
        for (int r = 0; r < 8; r++) {
            float4 a = *(const float4*)(xp + r * NS);
            float4 b = *(const float4*)(xp + r * NS + 4);
            s += a.x + a.y + a.z + a.w + b.x + b.y + b.z + b.w;
        }
        ll3[sub][tt] = s * 0.125f;
        __syncthreads();
        if (tt < 16) {
            int xy = tt;
            int xx = xy >> 2, yy = xy & 3;
            float a = ll3[sub][(2 * xx) * 8 + 2 * yy];
            float b = ll3[sub][(2 * xx) * 8 + 2 * yy + 1];
            float c = ll3[sub][(2 * xx + 1) * 8 + 2 * yy];
            float d = ll3[sub][(2 * xx + 1) * 8 + 2 * yy + 1];
            int bb = bc >> 6, ch = bc & 63;
            float v[4];
            v[0] = (a + b + c + d) * 0.5f;
            v[1] = (a + b - c - d) * 0.5f;
            v[2] = (a - b + c - d) * 0.5f;
            v[3] = (a - b - c + d) * 0.5f;
#pragma unroll
            for (int band = 0; band < 4; band++)
                g_c[((band * 16 + xy) * 64 + ch) * 32 + bb] = v[band];
        }
    }
}

// ---------------------------------------------------------------------------
// kB1: one block per (band,xy,e): S_e[b,o] = sum_i (w_e[b]*c[i,b]) * W_e[i,o]
// (e==0 blocks also subtract Wt[b]*c[o,b]).  384 blocks x 256 threads,
// 8KB smem LHS, K=64, thread tile 2b x 4o.
// Output layout: g_S[b][xy][e*4+band][o].
// ---------------------------------------------------------------------------
__global__ void kB1(const float* __restrict__ lam) {
    __shared__ float wcsh[64 * 32];               // 8KB: [i][b] gate-scaled
    int blk = blockIdx.x;             // 0..383
    int e = blk % NE;
    int bx = blk / NE;
    int xy = bx & 15;
    int band = bx >> 4;
    int t = threadIdx.x;
    int bl = t & 31;

    const float* lp = lam + bl * 8;
    float we;
    if      (e == 0) we = lp[0];
    else if (e == 1) we = lp[1];
    else if (e == 2) we = lp[2];
    else if (e == 3) we = lp[3];
    else if (e == 4) we = lp[4] + lp[6];
    else             we = lp[5] + lp[7];

    const float* cbase = g_c + (size_t)(band * 16 + xy) * 2048;   // [i][b]
#pragma unroll
    for (int r = 0; r < 8; r++) {
        int j = t + 256 * r;
        wcsh[j] = cbase[j] * we;
    }
    __syncthreads();

    int b0 = (t >> 4) * 2;            // 0..30
    int o0 = (t & 15) * 4;            // 0..60
    const float* wbase = g_Wt2 + ((size_t)(band * 16 + xy) * NE + e) * 4096 + o0;
    float a0x = 0.f, a0y = 0.f, a0z = 0.f, a0w = 0.f;
    float a1x = 0.f, a1y = 0.f, a1z = 0.f, a1w = 0.f;
#pragma unroll 8
    for (int k = 0; k < 64; k++) {
        float2 c2 = *(const float2*)(wcsh + k * 32 + b0);
        float4 w4 = *(const float4*)(wbase + k * 64);
        a0x += c2.x * w4.x; a0y += c2.x * w4.y; a0z += c2.x * w4.z; a0w += c2.x * w4.w;
        a1x += c2.y * w4.x; a1y += c2.y * w4.y; a1z += c2.y * w4.z; a1w += c2.y * w4.w;
    }

    if (e == 0) {
        float Wt0 = g_Wsum[b0], Wt1 = g_Wsum[b0 + 1];
        a0x -= Wt0 * cbase[(o0    ) * 32 + b0];
        a0y -= Wt0 * cbase[(o0 + 1) * 32 + b0];
        a0z -= Wt0 * cbase[(o0 + 2) * 32 + b0];
        a0w -= Wt0 * cbase[(o0 + 3) * 32 + b0];
        a1x -= Wt1 * cbase[(o0    ) * 32 + b0 + 1];
        a1y -= Wt1 * cbase[(o0 + 1) * 32 + b0 + 1];
        a1z -= Wt1 * cbase[(o0 + 2) * 32 + b0 + 1];
        a1w -= Wt1 * cbase[(o0 + 3) * 32 + b0 + 1];
    }

    int eb = e * 4 + band;
    float* Sp = g_S + (((size_t)(b0 * 16 + xy)) * 24 + eb) * 64 + o0;
    *(float4*)Sp            = make_float4(a0x, a0y, a0z, a0w);
    *(float4*)(Sp + 24576)  = make_float4(a1x, a1y, a1z, a1w);   // b0+1 (stride 16*24*64)
}

// ---------------------------------------------------------------------------
// kC: fused expert-sum + IDWT + AXPY.  One block per (b,c) image.
// Threads 0..63: z[XY] = (1/16) * sum_e IDWT(S_e)  from g_S (L2-hot);
// then 4 warp-contiguous float4 slots per thread: out = Wsum*x + z.
// ---------------------------------------------------------------------------
__global__ void kC(const float* __restrict__ x, float* __restrict__ out) {
    __shared__ float zs[64];
    int bc = blockIdx.x;
    int t = threadIdx.x;
    int b = bc >> 6, c = bc & 63;

    if (t < 64) {
        int X = t >> 3, Y = t & 7;
        int xy = ((X >> 1) << 2) + (Y >> 1);
        float s1 = (X & 1) ? -1.f : 1.f;
        float s2 = (Y & 1) ? -1.f : 1.f;
        float s3 = s1 * s2;
        const float* p = g_S + ((size_t)(b * 16 + xy) * 24) * 64 + c;
        float z = 0.f;
#pragma unroll
        for (int e = 0; e < NE; e++) {
            float S0 = p[e * 256];
            float S1 = p[e * 256 + 64];
            float S2 = p[e * 256 + 128];
            float S3 = p[e * 256 + 192];
            z += S0 + s1 * S1 + s2 * S2 + s3 * S3;
        }
        zs[t] = z * 0.0625f;
    }
    float W = g_Wsum[b];
    __syncthreads();

    const float* xp = x + (size_t)bc * 4096;
    float* op = out + (size_t)bc * 4096;
#pragma unroll
    for (int k = 0; k < 4; k++) {
        int idx = (t << 2) + (k << 10);          // warp-contiguous within slot
        float zv = zs[((idx >> 9) << 3) + ((idx & 63) >> 3)];  // X*8 + Y
        float4 xv = *(const float4*)(xp + idx);
        float4 ov;
        ov.x = fmaf(W, xv.x, zv);
        ov.y = fmaf(W, xv.y, zv);
        ov.z = fmaf(W, xv.z, zv);
        ov.w = fmaf(W, xv.w, zv);
        *(float4*)(op + idx) = ov;
    }
}

// ---------------------------------------------------------------------------
extern "C" void kernel_launch(void* const* d_in, const int* in_sizes, int n_in,
                              void* d_out, int out_size) {
    const float* x   = (const float*)d_in[0];  // [32,64,64,64]
    const float* lam = (const float*)d_in[1];  // [32,1,8,1]
    const float* WL  = (const float*)d_in[2];  // [8,64,64,4,4]
    const float* WH  = (const float*)d_in[3];  // [8,3,64,64,4,4]
    float* out = (float*)d_out;

    kTA<<<896, 256>>>(x, WL, WH, lam);
    kB1<<<384, 256>>>(lam);
    kC<<<2048, 256>>>(x, out);
    (void)in_sizes; (void)n_in; (void)out_size;
}